// round 10
// baseline (speedup 1.0000x reference)
#include <cuda_runtime.h>
#include <cstdint>

// LocalAtten: NB=4, NLOC=2048, NNEI=64, NI=ND=64, NH=4
//   P[h] = Wq_h @ Wkv_k_h^T / 8   -> s[j,h] = g1 . P_h . gg1_j
//   M[h] = Wkv_v_h @ Wh_h         -> out = sum_h u_h @ M_h + bh
// R10: projections as real tiled GEMMs (W = g1 @ P_flat, out = U @ M_flat
// + bh), attention kernel keeps R9 phases minus W/out (reads d_W, writes
// d_U). Removes ~43% of the attention kernel's L1 wavefronts.

__device__ float d_Pf[64 * 256];    // [ip][h*64+i]
__device__ float d_M[256 * 64];     // [h*64+i][o]
__device__ float d_W[8192 * 256];   // [bl][h*64+i]
__device__ float d_U[8192 * 256];   // [bl][h*64+i]

typedef unsigned long long u64;

// ---- f32x2 helpers (carrier = u64 holding 2 packed floats) -----------------
__device__ __forceinline__ void ffma2(u64& d, u64 a, u64 b) {
    asm("fma.rn.f32x2 %0, %1, %2, %0;" : "+l"(d) : "l"(a), "l"(b));
}
__device__ __forceinline__ u64 pack2(float x, float y) {
    u64 d;
    asm("mov.b64 %0, {%1, %2};" : "=l"(d) : "f"(x), "f"(y));
    return d;
}
__device__ __forceinline__ float2 unpack2(u64 d) {
    float2 f;
    asm("mov.b64 {%0, %1}, %2;" : "=f"(f.x), "=f"(f.y) : "l"(d));
    return f;
}
__device__ __forceinline__ float hsum2(u64 d) {
    float2 f = unpack2(d);
    return f.x + f.y;
}

// ---------------------------------------------------------------------------
// Precompute P_flat and M_flat. grid (4 heads, 2 matrices), 256 threads.
// ---------------------------------------------------------------------------
__global__ __launch_bounds__(256) void la_precompute(
    const float* __restrict__ Wq,   // (64, 256)  col = d*4 + h
    const float* __restrict__ Wkv,  // (64, 512)  col = d*8 + c
    const float* __restrict__ Wh)   // (256, 64)  row = h*64 + d
{
    int h = blockIdx.x;
    int mat = blockIdx.y;
    int t = threadIdx.x;
    __shared__ float A[64][65];
    __shared__ float B[64][65];

    if (mat == 0) {
        for (int e = t; e < 4096; e += 256) {
            int r = e >> 6, d = e & 63;
            A[r][d] = Wq[r * 256 + d * 4 + h];
            B[r][d] = Wkv[r * 512 + d * 8 + h];
        }
        __syncthreads();
        for (int e = t; e < 4096; e += 256) {
            int ip = e >> 6, i = e & 63;
            float acc = 0.f;
#pragma unroll 8
            for (int d = 0; d < 64; d++) acc += A[ip][d] * B[i][d];
            d_Pf[ip * 256 + h * 64 + i] = acc * 0.125f;
        }
    } else {
        for (int e = t; e < 4096; e += 256) {
            int r = e >> 6, c = e & 63;
            A[r][c] = Wkv[r * 512 + c * 8 + 4 + h];
            B[r][c] = Wh[(h * 64 + r) * 64 + c];
        }
        __syncthreads();
        for (int e = t; e < 4096; e += 256) {
            int i = e >> 6, o = e & 63;
            float acc = 0.f;
#pragma unroll 8
            for (int d = 0; d < 64; d++) acc += A[i][d] * B[d][o];
            d_M[(h * 64 + i) * 64 + o] = acc;
        }
    }
}

// ---------------------------------------------------------------------------
// Tiled GEMM: C[R x N] = A[R x K] @ B[K x N] (+ bias). 256 threads = 16x16,
// tile BM x 64, micro-tile TM x 4 per thread, K chunks of 64.
// ---------------------------------------------------------------------------
template <int BM, int TM>
__global__ __launch_bounds__(256) void la_gemm(
    const float* __restrict__ A, const float* __restrict__ B,
    float* __restrict__ C, int K, int N, const float* __restrict__ bias)
{
    __shared__ __align__(16) float As[BM][68];
    __shared__ __align__(16) float Bs[64][68];
    int t = threadIdx.x;
    int tx = t & 15, ty = t >> 4;
    int rbase = blockIdx.x * BM, cbase = blockIdx.y * 64;

    u64 acc[TM][2];
#pragma unroll
    for (int i = 0; i < TM; i++) {
        acc[i][0] = pack2(0.f, 0.f);
        acc[i][1] = acc[i][0];
    }

    for (int kc = 0; kc < K; kc += 64) {
        if (kc) __syncthreads();
#pragma unroll
        for (int q = 0; q < TM; q++) {
            int e = t + q * 256;
            int row = e >> 4, k4 = (e & 15) << 2;
            *(float4*)&As[row][k4] =
                *(const float4*)&A[(size_t)(rbase + row) * K + kc + k4];
        }
#pragma unroll
        for (int q = 0; q < 4; q++) {
            int e = t + q * 256;
            int krow = e >> 4, c4 = (e & 15) << 2;
            *(float4*)&Bs[krow][c4] =
                *(const float4*)&B[(size_t)(kc + krow) * N + cbase + c4];
        }
        __syncthreads();

#pragma unroll
        for (int ks = 0; ks < 16; ks++) {
            float4 b0 = *(float4*)&Bs[ks * 4 + 0][tx * 4];
            float4 b1 = *(float4*)&Bs[ks * 4 + 1][tx * 4];
            float4 b2 = *(float4*)&Bs[ks * 4 + 2][tx * 4];
            float4 b3 = *(float4*)&Bs[ks * 4 + 3][tx * 4];
            u64 bp00 = pack2(b0.x, b0.y), bp01 = pack2(b0.z, b0.w);
            u64 bp10 = pack2(b1.x, b1.y), bp11 = pack2(b1.z, b1.w);
            u64 bp20 = pack2(b2.x, b2.y), bp21 = pack2(b2.z, b2.w);
            u64 bp30 = pack2(b3.x, b3.y), bp31 = pack2(b3.z, b3.w);
#pragma unroll
            for (int i = 0; i < TM; i++) {
                float4 av = *(float4*)&As[ty * TM + i][ks * 4];
                u64 ax = pack2(av.x, av.x);
                ffma2(acc[i][0], ax, bp00); ffma2(acc[i][1], ax, bp01);
                u64 ay = pack2(av.y, av.y);
                ffma2(acc[i][0], ay, bp10); ffma2(acc[i][1], ay, bp11);
                u64 az = pack2(av.z, av.z);
                ffma2(acc[i][0], az, bp20); ffma2(acc[i][1], az, bp21);
                u64 aw = pack2(av.w, av.w);
                ffma2(acc[i][0], aw, bp30); ffma2(acc[i][1], aw, bp31);
            }
        }
    }

    int cc = cbase + tx * 4;
    float4 bv = make_float4(0.f, 0.f, 0.f, 0.f);
    if (bias) bv = *(const float4*)&bias[cc];
#pragma unroll
    for (int i = 0; i < TM; i++) {
        float2 lo = unpack2(acc[i][0]), hi = unpack2(acc[i][1]);
        float4 v = make_float4(lo.x + bv.x, lo.y + bv.y, hi.x + bv.z, hi.y + bv.w);
        *(float4*)&C[(size_t)(rbase + ty * TM + i) * N + cc] = v;
    }
}

// ---------------------------------------------------------------------------
// Attention: one CTA per 4 locs. 2048 CTAs x 256 threads.
// Reads d_W, writes d_U.
// ---------------------------------------------------------------------------
__global__ __launch_bounds__(256) void la_attn4(
    const float* __restrict__ gg1,  // (8192, 64, 64)
    const int* __restrict__ msk)    // (8192, 64) int32 bool
{
    __shared__ __align__(16) float ggS[64 * 64];     // swizzled tile, 16KB
    __shared__ __align__(16) float Wl[4][256];       // [l][h*64+i]
    __shared__ __align__(16) float aw[256];          // [j*4 + h]
    __shared__ __align__(16) float partT[16][68];    // [(q*4+h)][j or i]
    __shared__ int idxs[4][64];
    __shared__ int mcnt[4];

    int g = blockIdx.x;
    int t = threadIdx.x;
    int lane = t & 31, wid = t >> 5;

    // W rows for the 4 locs: 1024 contiguous floats
    ((float4*)Wl)[t] = ((const float4*)(d_W + (size_t)g * 1024))[t];

    // mask compaction: one warp per loc
    if (wid < 4) {
        const int* mp = msk + (size_t)(g * 4 + wid) * 64;
        int base = 0;
#pragma unroll
        for (int c = 0; c < 2; c++) {
            int j = c * 32 + lane;
            bool bit = mp[j] != 0;
            unsigned bal = __ballot_sync(0xffffffffu, bit);
            int pos = base + __popc(bal & ((1u << lane) - 1u));
            if (bit) idxs[wid][pos] = j;
            base += __popc(bal);
        }
        if (lane == 0) mcnt[wid] = base;
    }
    __syncthreads();

    for (int l = 0; l < 4; l++) {
        int m = mcnt[l];

        // gather unmasked rows into swizzled tile (float4 slot = qq ^ (jj&15))
        const float* ggb = gg1 + (size_t)(g * 4 + l) * 4096;
        float4* ggS4 = (float4*)ggS;
        for (int e = t; e < m * 16; e += 256) {
            int jj = e >> 4, qq = e & 15;
            float4 v = *(const float4*)(ggb + idxs[l][jj] * 64 + qq * 4);
            ggS4[jj * 16 + (qq ^ (jj & 15))] = v;
        }
        __syncthreads();  // orders gather (and Wl on first iter)

        // logits: thread (q = t>>6, j = t&63) handles i in [16q,16q+16), 4 heads
        {
            int q = t >> 6, j = t & 63, jx = j & 15;
            u64 a0 = pack2(0.f, 0.f), a1 = a0, a2 = a0, a3 = a0;
            const ulonglong2* wd = (const ulonglong2*)Wl[l];
            const ulonglong2* gd = (const ulonglong2*)ggS;
#pragma unroll
            for (int k = 0; k < 4; k++) {
                int qq = q * 4 + k;
                ulonglong2 gv = gd[j * 16 + (qq ^ jx)];
                ulonglong2 w0 = wd[qq];
                ulonglong2 w1 = wd[16 + qq];
                ulonglong2 w2 = wd[32 + qq];
                ulonglong2 w3 = wd[48 + qq];
                ffma2(a0, gv.x, w0.x); ffma2(a0, gv.y, w0.y);
                ffma2(a1, gv.x, w1.x); ffma2(a1, gv.y, w1.y);
                ffma2(a2, gv.x, w2.x); ffma2(a2, gv.y, w2.y);
                ffma2(a3, gv.x, w3.x); ffma2(a3, gv.y, w3.y);
            }
            partT[q * 4 + 0][j] = hsum2(a0);
            partT[q * 4 + 1][j] = hsum2(a1);
            partT[q * 4 + 2][j] = hsum2(a2);
            partT[q * 4 + 3][j] = hsum2(a3);
        }
        __syncthreads();

        // softmax: warp per head over compacted j (combine quarters inline)
        if (t < 128) {
            int h = t >> 5, ln = t & 31;
            float x0 = -1e30f, x1 = -1e30f;
            if (ln < m)
                x0 = partT[h][ln] + partT[4 + h][ln] + partT[8 + h][ln] + partT[12 + h][ln];
            if (ln + 32 < m)
                x1 = partT[h][ln + 32] + partT[4 + h][ln + 32] + partT[8 + h][ln + 32] + partT[12 + h][ln + 32];
            float mx = fmaxf(x0, x1);
#pragma unroll
            for (int off = 16; off; off >>= 1)
                mx = fmaxf(mx, __shfl_xor_sync(0xffffffffu, mx, off));
            float e0 = (ln < m) ? __expf(x0 - mx) : 0.f;
            float e1 = (ln + 32 < m) ? __expf(x1 - mx) : 0.f;
            float s = e0 + e1;
#pragma unroll
            for (int off = 16; off; off >>= 1)
                s += __shfl_xor_sync(0xffffffffu, s, off);
            float inv = (s > 0.f) ? 1.f / s : 0.f;
            aw[ln * 4 + h] = e0 * inv;
            aw[(ln + 32) * 4 + h] = e1 * inv;
        }
        __syncthreads();

        // u: thread (q = t>>6, i = t&63) handles quarter of j-range, 4 heads
        {
            int q = t >> 6, i = t & 63;
            int ihi = i >> 2, ilo = i & 3;
            int j0 = (m * q) >> 2, j1 = (m * (q + 1)) >> 2;
            u64 u01 = pack2(0.f, 0.f), u23 = u01;
            const ulonglong2* ad = (const ulonglong2*)aw;  // ad[j] = {h01, h23}
            for (int j = j0; j < j1; j++) {
                ulonglong2 a = ad[j];
                float v = ggS[j * 64 + ((ihi ^ (j & 15)) << 2) + ilo];
                u64 vb = pack2(v, v);
                ffma2(u01, vb, a.x);
                ffma2(u23, vb, a.y);
            }
            float2 f01 = unpack2(u01), f23 = unpack2(u23);
            partT[q * 4 + 0][i] = f01.x;
            partT[q * 4 + 1][i] = f01.y;
            partT[q * 4 + 2][i] = f23.x;
            partT[q * 4 + 3][i] = f23.y;
        }
        __syncthreads();

        {   // combine quarters, write U row (t = h*64+i)
            int h = t >> 6, i = t & 63;
            d_U[(size_t)(g * 4 + l) * 256 + t] =
                partT[h][i] + partT[4 + h][i] + partT[8 + h][i] + partT[12 + h][i];
        }
        __syncthreads();  // ggS + partT free for next loc
    }
}

// ---------------------------------------------------------------------------
extern "C" void kernel_launch(void* const* d_in, const int* in_sizes, int n_in,
                              void* d_out, int out_size)
{
    const float* g1 = (const float*)d_in[0];
    const float* gg1 = (const float*)d_in[1];
    const int* msk = (const int*)d_in[2];
    const float* Wq = (const float*)d_in[3];
    const float* Wkv = (const float*)d_in[4];
    const float* Wh = (const float*)d_in[5];
    const float* bh = (const float*)d_in[6];
    float* out = (float*)d_out;

    float* pPf; cudaGetSymbolAddress((void**)&pPf, d_Pf);
    float* pM;  cudaGetSymbolAddress((void**)&pM, d_M);
    float* pW;  cudaGetSymbolAddress((void**)&pW, d_W);
    float* pU;  cudaGetSymbolAddress((void**)&pU, d_U);

    la_precompute<<<dim3(4, 2), 256>>>(Wq, Wkv, Wh);
    la_gemm<64, 4><<<dim3(128, 4), 256>>>(g1, pPf, pW, 64, 256, nullptr);
    la_attn4<<<2048, 256>>>(gg1, msk);
    la_gemm<32, 2><<<dim3(256, 1), 256>>>(pU, pM, out, 256, 64, bh);
}

// round 11
// speedup vs baseline: 1.1579x; 1.1579x over previous
#include <cuda_runtime.h>
#include <cstdint>

// LocalAtten: NB=4, NLOC=2048, NNEI=64, NI=ND=64, NH=4
//   P[h] = Wq_h @ Wkv_k_h^T / 8   -> s[j,h] = g1 . P_h . gg1_j
//   M[h] = Wkv_v_h @ Wh_h         -> out = sum_h u_h @ M_h + bh
// R11: R9 fused kernel + cp.async double-buffered gg1 gather pipeline.
// Gathers for loc l+2 are issued after compute of loc l finishes, hiding
// DRAM latency behind a full iteration of compute. Splits (R8/R10) are dead:
// projection kernels are grid-limited at <2 CTA/SM.

__device__ float d_P[4 * 64 * 64];  // [h][ip][i]
__device__ float d_M[4 * 64 * 64];  // [h][i][o]

typedef unsigned long long u64;

// ---- f32x2 helpers (carrier = u64 holding 2 packed floats) -----------------
__device__ __forceinline__ void ffma2(u64& d, u64 a, u64 b) {
    asm("fma.rn.f32x2 %0, %1, %2, %0;" : "+l"(d) : "l"(a), "l"(b));
}
__device__ __forceinline__ u64 pack2(float x, float y) {
    u64 d;
    asm("mov.b64 %0, {%1, %2};" : "=l"(d) : "f"(x), "f"(y));
    return d;
}
__device__ __forceinline__ float2 unpack2(u64 d) {
    float2 f;
    asm("mov.b64 {%0, %1}, %2;" : "=f"(f.x), "=f"(f.y) : "l"(d));
    return f;
}
__device__ __forceinline__ float hsum2(u64 d) {
    float2 f = unpack2(d);
    return f.x + f.y;
}

// ---- cp.async helpers ------------------------------------------------------
__device__ __forceinline__ void cp_async16(void* smem_dst, const void* gmem_src) {
    unsigned dst = (unsigned)__cvta_generic_to_shared(smem_dst);
    asm volatile("cp.async.cg.shared.global [%0], [%1], 16;"
                 :: "r"(dst), "l"(gmem_src) : "memory");
}
__device__ __forceinline__ void cp_commit() {
    asm volatile("cp.async.commit_group;" ::: "memory");
}
template <int N>
__device__ __forceinline__ void cp_wait() {
    asm volatile("cp.async.wait_group %0;" :: "n"(N) : "memory");
}

// ---------------------------------------------------------------------------
// Precompute P and M. grid (4 heads, 2 matrices), 256 threads.
// ---------------------------------------------------------------------------
__global__ __launch_bounds__(256) void la_precompute(
    const float* __restrict__ Wq,   // (64, 256)  col = d*4 + h
    const float* __restrict__ Wkv,  // (64, 512)  col = d*8 + c
    const float* __restrict__ Wh)   // (256, 64)  row = h*64 + d
{
    int h = blockIdx.x;
    int mat = blockIdx.y;
    int t = threadIdx.x;
    __shared__ float A[64][65];
    __shared__ float B[64][65];

    if (mat == 0) {
        for (int e = t; e < 4096; e += 256) {
            int r = e >> 6, d = e & 63;
            A[r][d] = Wq[r * 256 + d * 4 + h];
            B[r][d] = Wkv[r * 512 + d * 8 + h];
        }
        __syncthreads();
        for (int e = t; e < 4096; e += 256) {
            int ip = e >> 6, i = e & 63;
            float acc = 0.f;
#pragma unroll 8
            for (int d = 0; d < 64; d++) acc += A[ip][d] * B[i][d];
            d_P[(h * 64 + ip) * 64 + i] = acc * 0.125f;
        }
    } else {
        for (int e = t; e < 4096; e += 256) {
            int r = e >> 6, c = e & 63;
            A[r][c] = Wkv[r * 512 + c * 8 + 4 + h];
            B[r][c] = Wh[(h * 64 + r) * 64 + c];
        }
        __syncthreads();
        for (int e = t; e < 4096; e += 256) {
            int i = e >> 6, o = e & 63;
            float acc = 0.f;
#pragma unroll 8
            for (int d = 0; d < 64; d++) acc += A[i][d] * B[d][o];
            d_M[(h * 64 + i) * 64 + o] = acc;
        }
    }
}

// ---------------------------------------------------------------------------
// Fused main kernel: one CTA per 4 locs. 2048 CTAs x 256 threads.
// ---------------------------------------------------------------------------
__global__ __launch_bounds__(256) void la_fused(
    const float* __restrict__ g1,   // (8192, 64)
    const float* __restrict__ gg1,  // (8192, 64, 64)
    const int* __restrict__ msk,    // (8192, 64) int32 bool
    const float* __restrict__ bh,   // (64,)
    float* __restrict__ out)        // (8192, 64)
{
    __shared__ __align__(16) float ggS[2][64 * 64];  // 2 swizzled tiles, 32KB
    __shared__ __align__(16) float Wl[4][256];       // [l][h*64+i]
    __shared__ __align__(16) float g1T[64 * 4];      // [ip*4 + l]
    __shared__ __align__(16) float uT[256 * 4];      // [(h*64+i)*4 + l]
    __shared__ __align__(16) float aw[256];          // [j*4 + h]
    __shared__ __align__(16) float partT[16][66];    // [(q*4+h)][j or i]
    __shared__ int idxs[4][64];
    __shared__ int mcnt[4];

    int g = blockIdx.x;
    int t = threadIdx.x;
    int lane = t & 31, wid = t >> 5;

    // --- mask compaction: one warp per loc ---
    if (wid < 4) {
        const int* mp = msk + (size_t)(g * 4 + wid) * 64;
        int base = 0;
#pragma unroll
        for (int c = 0; c < 2; c++) {
            int j = c * 32 + lane;
            bool bit = mp[j] != 0;
            unsigned bal = __ballot_sync(0xffffffffu, bit);
            int pos = base + __popc(bal & ((1u << lane) - 1u));
            if (bit) idxs[wid][pos] = j;
            base += __popc(bal);
        }
        if (lane == 0) mcnt[wid] = base;
    }
    // --- g1 transposed staging: g1T[ip*4+l] = g1[loc l][ip] ---
    {
        int l = t >> 6, ip = t & 63;
        g1T[ip * 4 + l] = g1[(size_t)(g * 4 + l) * 64 + ip];
    }
    __syncthreads();  // idxs/mcnt visible to all for async gathers

    // --- async gathers for loc 0 and loc 1 (groups G0, G1) ---
#pragma unroll
    for (int pl = 0; pl < 2; pl++) {
        const float* ggb = gg1 + (size_t)(g * 4 + pl) * 4096;
        int lim = mcnt[pl] * 16;
        for (int e = t; e < lim; e += 256) {
            int jj = e >> 4, qq = e & 15;
            cp_async16(&ggS[pl][(jj * 16 + (qq ^ (jj & 15))) * 4],
                       ggb + idxs[pl][jj] * 64 + qq * 4);
        }
        cp_commit();
    }

    // --- W phase, batched over 4 locs, f32x2 (overlaps G0/G1 gathers) ---
    {   // thread (h = t>>6, i = t&63)
        int h = t >> 6, i = t & 63;
        const float* Pp = d_P + h * 4096 + i;
        const ulonglong2* gd = (const ulonglong2*)g1T;  // gd[ip] = {l01, l23}
        u64 a01 = pack2(0.f, 0.f), a23 = a01;
#pragma unroll 8
        for (int ip = 0; ip < 64; ip++) {
            float p = Pp[ip * 64];
            u64 pb = pack2(p, p);
            ulonglong2 gv = gd[ip];
            ffma2(a01, gv.x, pb);
            ffma2(a23, gv.y, pb);
        }
        float2 f01 = unpack2(a01), f23 = unpack2(a23);
        Wl[0][t] = f01.x;
        Wl[1][t] = f01.y;
        Wl[2][t] = f23.x;
        Wl[3][t] = f23.y;
    }

    // --- per-loc attention, software-pipelined gathers ---
#pragma unroll
    for (int l = 0; l < 4; l++) {
        const float* buf = ggS[l & 1];

        // wait for this loc's tile (keep 1 newer group in flight), publish
        if (l < 3) cp_wait<1>(); else cp_wait<0>();
        __syncthreads();  // tile + Wl (first iter) visible CTA-wide

        int m = mcnt[l];

        // logits: thread (q = t>>6, j = t&63) handles i in [16q,16q+16), 4 heads
        {
            int q = t >> 6, j = t & 63, jx = j & 15;
            u64 a0 = pack2(0.f, 0.f), a1 = a0, a2 = a0, a3 = a0;
            const ulonglong2* wd = (const ulonglong2*)Wl[l];
            const ulonglong2* gd = (const ulonglong2*)buf;
#pragma unroll
            for (int k = 0; k < 4; k++) {
                int qq = q * 4 + k;
                ulonglong2 gv = gd[j * 16 + (qq ^ jx)];
                ulonglong2 w0 = wd[qq];
                ulonglong2 w1 = wd[16 + qq];
                ulonglong2 w2 = wd[32 + qq];
                ulonglong2 w3 = wd[48 + qq];
                ffma2(a0, gv.x, w0.x); ffma2(a0, gv.y, w0.y);
                ffma2(a1, gv.x, w1.x); ffma2(a1, gv.y, w1.y);
                ffma2(a2, gv.x, w2.x); ffma2(a2, gv.y, w2.y);
                ffma2(a3, gv.x, w3.x); ffma2(a3, gv.y, w3.y);
            }
            partT[q * 4 + 0][j] = hsum2(a0);
            partT[q * 4 + 1][j] = hsum2(a1);
            partT[q * 4 + 2][j] = hsum2(a2);
            partT[q * 4 + 3][j] = hsum2(a3);
        }
        __syncthreads();

        // softmax: warp per head over compacted j (combine quarters inline)
        if (t < 128) {
            int h = t >> 5, ln = t & 31;
            float x0 = -1e30f, x1 = -1e30f;
            if (ln < m)
                x0 = partT[h][ln] + partT[4 + h][ln] + partT[8 + h][ln] + partT[12 + h][ln];
            if (ln + 32 < m)
                x1 = partT[h][ln + 32] + partT[4 + h][ln + 32] + partT[8 + h][ln + 32] + partT[12 + h][ln + 32];
            float mx = fmaxf(x0, x1);
#pragma unroll
            for (int off = 16; off; off >>= 1)
                mx = fmaxf(mx, __shfl_xor_sync(0xffffffffu, mx, off));
            float e0 = (ln < m) ? __expf(x0 - mx) : 0.f;
            float e1 = (ln + 32 < m) ? __expf(x1 - mx) : 0.f;
            float s = e0 + e1;
#pragma unroll
            for (int off = 16; off; off >>= 1)
                s += __shfl_xor_sync(0xffffffffu, s, off);
            float inv = (s > 0.f) ? 1.f / s : 0.f;
            aw[ln * 4 + h] = e0 * inv;
            aw[(ln + 32) * 4 + h] = e1 * inv;
        }
        __syncthreads();

        // u: thread (q = t>>6, i = t&63) handles quarter of j-range, 4 heads
        {
            int q = t >> 6, i = t & 63;
            int ihi = i >> 2, ilo = i & 3;
            int j0 = (m * q) >> 2, j1 = (m * (q + 1)) >> 2;
            u64 u01 = pack2(0.f, 0.f), u23 = u01;
            const ulonglong2* ad = (const ulonglong2*)aw;  // ad[j] = {h01, h23}
            for (int j = j0; j < j1; j++) {
                ulonglong2 a = ad[j];
                float v = buf[j * 64 + ((ihi ^ (j & 15)) << 2) + ilo];
                u64 vb = pack2(v, v);
                ffma2(u01, vb, a.x);
                ffma2(u23, vb, a.y);
            }
            float2 f01 = unpack2(u01), f23 = unpack2(u23);
            partT[q * 4 + 0][i] = f01.x;
            partT[q * 4 + 1][i] = f01.y;
            partT[q * 4 + 2][i] = f23.x;
            partT[q * 4 + 3][i] = f23.y;
        }
        __syncthreads();

        {   // combine quarters into uT: t = h*64+i
            int h = t >> 6, i = t & 63;
            uT[t * 4 + l] =
                partT[h][i] + partT[4 + h][i] + partT[8 + h][i] + partT[12 + h][i];
        }
        __syncthreads();  // all reads of buf done; partT consumed

        // issue async gather for loc l+2 into the buffer just freed
        if (l + 2 < 4) {
            int nl = l + 2;
            const float* ggb = gg1 + (size_t)(g * 4 + nl) * 4096;
            int lim = mcnt[nl] * 16;
            for (int e = t; e < lim; e += 256) {
                int jj = e >> 4, qq = e & 15;
                cp_async16(&ggS[nl & 1][(jj * 16 + (qq ^ (jj & 15))) * 4],
                           ggb + idxs[nl][jj] * 64 + qq * 4);
            }
            cp_commit();
        }
    }

    // --- out phase, batched over 4 locs, f32x2 ---
    {   // thread (h = t>>6, o = t&63)
        int h = t >> 6, o = t & 63;
        const float* Mp = d_M + h * 4096 + o;
        const ulonglong2* ud = (const ulonglong2*)uT + h * 64;  // ud[i] = {l01, l23}
        u64 a01 = pack2(0.f, 0.f), a23 = a01;
#pragma unroll 8
        for (int i = 0; i < 64; i++) {
            float mv = Mp[i * 64];
            u64 mb = pack2(mv, mv);
            ulonglong2 uv = ud[i];
            ffma2(a01, uv.x, mb);
            ffma2(a23, uv.y, mb);
        }
        // stash per-head partial in partT-compatible scratch (reuse Wl)
        float2 f01 = unpack2(a01), f23 = unpack2(a23);
        Wl[h][o * 4 + 0] = f01.x;  // Wl reused: [h][o*4 + l]
        Wl[h][o * 4 + 1] = f01.y;
        Wl[h][o * 4 + 2] = f23.x;
        Wl[h][o * 4 + 3] = f23.y;
    }
    __syncthreads();

    // final: (l = t>>6, o = t&63); sum heads + bias
    {
        int l = t >> 6, o = t & 63;
        float v = bh[o] + Wl[0][o * 4 + l] + Wl[1][o * 4 + l] +
                  Wl[2][o * 4 + l] + Wl[3][o * 4 + l];
        out[(size_t)(g * 4 + l) * 64 + o] = v;
    }
}

// ---------------------------------------------------------------------------
extern "C" void kernel_launch(void* const* d_in, const int* in_sizes, int n_in,
                              void* d_out, int out_size)
{
    const float* g1 = (const float*)d_in[0];
    const float* gg1 = (const float*)d_in[1];
    const int* msk = (const int*)d_in[2];
    const float* Wq = (const float*)d_in[3];
    const float* Wkv = (const float*)d_in[4];
    const float* Wh = (const float*)d_in[5];
    const float* bh = (const float*)d_in[6];
    float* out = (float*)d_out;

    la_precompute<<<dim3(4, 2), 256>>>(Wq, Wkv, Wh);
    la_fused<<<2048, 256>>>(g1, gg1, msk, bh, out);
}